// round 1
// baseline (speedup 1.0000x reference)
#include <cuda_runtime.h>
#include <cstdint>

// Output layout (per reference return order):
//   [0,            N*D)        mean_messages  (float)
//   [N*D,          N*D + N)    last_timestamps (float)
//   [N*D + N,      N*D + 2N)   counts (float)

__global__ void zero_out_kernel(float4* __restrict__ out4, long long n4) {
    long long i = (long long)blockIdx.x * blockDim.x + threadIdx.x;
    if (i < n4) out4[i] = make_float4(0.f, 0.f, 0.f, 0.f);
}

__global__ void zero_tail_kernel(float* __restrict__ out, long long start, long long n) {
    long long i = start + (long long)blockIdx.x * blockDim.x + threadIdx.x;
    if (i < n) out[i] = 0.f;
}

// One event handled by 64 consecutive threads (2 warps' halves); each thread
// owns 4 contiguous floats of the 256-wide message row. D assumed 256 here
// (asserted via launch math on host side: D/4 threads per event).
__global__ void scatter_kernel(const int* __restrict__ node_ids,
                               const float4* __restrict__ messages4,
                               const float* __restrict__ timestamps,
                               float* __restrict__ sums,      // [N, D]
                               float* __restrict__ last_ts,   // [N]
                               float* __restrict__ counts,    // [N]
                               int B, int Dq /* = D/4 */) {
    // blockDim.x = 256 -> (256 / Dq) events per block when Dq <= 256
    int events_per_block = blockDim.x / Dq;
    int local_e = threadIdx.x / Dq;
    int q = threadIdx.x - local_e * Dq;
    long long e = (long long)blockIdx.x * events_per_block + local_e;
    if (e >= B) return;

    int n = node_ids[e];
    float4 m = messages4[e * Dq + q];

    float* dst = sums + ((long long)n * Dq + q) * 4;
    asm volatile("red.global.add.v4.f32 [%0], {%1, %2, %3, %4};"
                 :: "l"(dst), "f"(m.x), "f"(m.y), "f"(m.z), "f"(m.w)
                 : "memory");

    if (q == 0) {
        atomicAdd(&counts[n], 1.0f);
        // timestamps >= 0, so integer max on the bit pattern == float max
        float t = timestamps[e];
        atomicMax((int*)&last_ts[n], __float_as_int(t));
    }
}

__global__ void finalize_kernel(float4* __restrict__ sums4,      // [N, D/4]
                                const float* __restrict__ counts, // [N]
                                int Nn, int Dq) {
    long long gid = (long long)blockIdx.x * blockDim.x + threadIdx.x;
    long long total = (long long)Nn * Dq;
    if (gid >= total) return;
    int n = (int)(gid / Dq);
    float c = counts[n];
    float s = 1.0f / fmaxf(c, 1.0f);
    float4 v = sums4[gid];
    v.x *= s; v.y *= s; v.z *= s; v.w *= s;
    sums4[gid] = v;
}

extern "C" void kernel_launch(void* const* d_in, const int* in_sizes, int n_in,
                              void* d_out, int out_size) {
    const int*   node_ids   = (const int*)  d_in[0];
    const float* messages   = (const float*)d_in[1];
    const float* timestamps = (const float*)d_in[2];
    // d_in[3] = n_nodes scalar on device; derive sizes on host instead.

    const int B = in_sizes[0];
    const int D = in_sizes[1] / B;            // 256
    const int N = out_size / (D + 2);         // 100000
    const int Dq = D / 4;                     // 64

    float* out      = (float*)d_out;
    float* sums     = out;                    // [N, D]
    float* last_ts  = out + (long long)N * D; // [N]
    float* counts   = last_ts + N;            // [N]

    // --- zero init: bulk float4 + scalar tail ---
    long long total = (long long)out_size;
    long long n4 = total / 4;
    {
        int thr = 256;
        long long blocks = (n4 + thr - 1) / thr;
        zero_out_kernel<<<(unsigned)blocks, thr>>>((float4*)out, n4);
        long long tail_start = n4 * 4;
        if (tail_start < total) {
            long long tail = total - tail_start;
            zero_tail_kernel<<<1, 256>>>(out, tail_start, total);
            (void)tail;
        }
    }

    // --- scatter ---
    {
        int thr = 256;
        int events_per_block = thr / Dq;      // 4 for D=256
        long long blocks = ((long long)B + events_per_block - 1) / events_per_block;
        scatter_kernel<<<(unsigned)blocks, thr>>>(node_ids, (const float4*)messages,
                                                  timestamps, sums, last_ts, counts,
                                                  B, Dq);
    }

    // --- finalize (divide by counts) ---
    {
        int thr = 256;
        long long total_q = (long long)N * Dq;
        long long blocks = (total_q + thr - 1) / thr;
        finalize_kernel<<<(unsigned)blocks, thr>>>((float4*)sums, counts, N, Dq);
    }
}

// round 2
// speedup vs baseline: 1.7946x; 1.7946x over previous
#include <cuda_runtime.h>
#include <cstdint>

// Output layout:
//   [0,       N*D)      mean_messages (float)
//   [N*D,     N*D+N)    last_timestamps (float)
//   [N*D+N,   N*D+2N)   counts (float)
//
// Strategy: counting-sort events by node id, then one warp per node gathers
// and sums its own message rows in registers. No float atomics on the wide data.

#define MAX_B (1 << 21)   // up to 2M events
#define MAX_N (1 << 18)   // up to 256k nodes
#define SCAN_BLK 1024

__device__ int g_hist[MAX_N];
__device__ int g_off[MAX_N];
__device__ int g_cur[MAX_N];
__device__ int g_order[MAX_B];
__device__ int g_bsum[SCAN_BLK];

// ---------------- zero: hist + last_ts ----------------
__global__ void zero_kernel(float* __restrict__ last_ts, int N) {
    int i = blockIdx.x * blockDim.x + threadIdx.x;
    if (i < N) { g_hist[i] = 0; last_ts[i] = 0.0f; }
}

// ---------------- histogram + last-timestamp ----------------
__global__ void hist_kernel(const int* __restrict__ ids,
                            const float* __restrict__ ts,
                            float* __restrict__ last_ts, int B) {
    int e = blockIdx.x * blockDim.x + threadIdx.x;
    if (e >= B) return;
    int n = ids[e];
    atomicAdd(&g_hist[n], 1);
    // timestamps >= 0 -> int-bitwise max == float max
    atomicMax((int*)&last_ts[n], __float_as_int(ts[e]));
}

// ---------------- block scan utility ----------------
__device__ __forceinline__ int block_excl_scan(int v, int tid, int* total) {
    int lane = tid & 31, wid = tid >> 5;
    int inc = v;
    #pragma unroll
    for (int d = 1; d < 32; d <<= 1) {
        int t = __shfl_up_sync(0xffffffffu, inc, d);
        if (lane >= d) inc += t;
    }
    __shared__ int wsum[32];
    if (lane == 31) wsum[wid] = inc;
    __syncthreads();
    if (wid == 0) {
        int w = wsum[lane];
        #pragma unroll
        for (int d = 1; d < 32; d <<= 1) {
            int t = __shfl_up_sync(0xffffffffu, w, d);
            if (lane >= d) w += t;
        }
        wsum[lane] = w;
    }
    __syncthreads();
    int excl = inc - v + (wid > 0 ? wsum[wid - 1] : 0);
    if (total) *total = wsum[31];
    return excl;
}

// scan pass 1: per-block exclusive scan of g_hist -> g_off, block totals -> g_bsum
__global__ void scan1_kernel(int N) {
    int tid = threadIdx.x;
    int i = blockIdx.x * SCAN_BLK + tid;
    int v = (i < N) ? g_hist[i] : 0;
    __shared__ int blk_total;
    int tot;
    int excl = block_excl_scan(v, tid, &tot);
    if (tid == 0) blk_total = tot;
    __syncthreads();
    if (i < N) g_off[i] = excl;
    if (tid == 0) g_bsum[blockIdx.x] = blk_total;
}

// scan pass 2: single block, exclusive scan of block totals in place
__global__ void scan2_kernel(int NB) {
    int tid = threadIdx.x;
    int v = (tid < NB) ? g_bsum[tid] : 0;
    int excl = block_excl_scan(v, tid, nullptr);
    if (tid < NB) g_bsum[tid] = excl;
}

// scan pass 3: add block offsets; also initialize cursors
__global__ void scan3_kernel(int N) {
    int i = blockIdx.x * SCAN_BLK + threadIdx.x;
    if (i >= N) return;
    int o = g_off[i] + g_bsum[blockIdx.x];
    g_off[i] = o;
    g_cur[i] = o;
}

// ---------------- binning: scatter event indices into node bins ----------------
__global__ void bin_kernel(const int* __restrict__ ids, int B) {
    int e = blockIdx.x * blockDim.x + threadIdx.x;
    if (e >= B) return;
    int n = ids[e];
    int pos = atomicAdd(&g_cur[n], 1);
    g_order[pos] = e;
}

// ---------------- gather-sum: one warp per node ----------------
__global__ void sum_kernel(const float4* __restrict__ messages4, // [B, 64]
                           float4* __restrict__ sums4,           // [N, 64]
                           float* __restrict__ counts,           // [N]
                           int N, int Dq /* = D/4 = 64 */) {
    int warp = blockIdx.x * (blockDim.x >> 5) + (threadIdx.x >> 5);
    int lane = threadIdx.x & 31;
    if (warp >= N) return;
    int n = warp;

    int c = g_hist[n];
    int start = g_off[n];

    float4 a0 = make_float4(0.f, 0.f, 0.f, 0.f);
    float4 a1 = make_float4(0.f, 0.f, 0.f, 0.f);

    for (int base = 0; base < c; base += 32) {
        int m = min(32, c - base);
        int idx = (lane < m) ? __ldg(&g_order[start + base + lane]) : 0;
        for (int k = 0; k < m; k++) {
            int e = __shfl_sync(0xffffffffu, idx, k);
            const float4* row = messages4 + (long long)e * Dq;
            float4 r0 = __ldg(&row[lane]);
            float4 r1 = __ldg(&row[lane + 32]);
            a0.x += r0.x; a0.y += r0.y; a0.z += r0.z; a0.w += r0.w;
            a1.x += r1.x; a1.y += r1.y; a1.z += r1.z; a1.w += r1.w;
        }
    }

    float inv = 1.0f / fmaxf((float)c, 1.0f);
    a0.x *= inv; a0.y *= inv; a0.z *= inv; a0.w *= inv;
    a1.x *= inv; a1.y *= inv; a1.z *= inv; a1.w *= inv;

    float4* dst = sums4 + (long long)n * Dq;
    dst[lane]      = a0;
    dst[lane + 32] = a1;
    if (lane == 0) counts[n] = (float)c;
}

extern "C" void kernel_launch(void* const* d_in, const int* in_sizes, int n_in,
                              void* d_out, int out_size) {
    const int*   node_ids   = (const int*)  d_in[0];
    const float* messages   = (const float*)d_in[1];
    const float* timestamps = (const float*)d_in[2];

    const int B = in_sizes[0];
    const int D = in_sizes[1] / B;            // 256
    const int N = out_size / (D + 2);         // 100000
    const int Dq = D / 4;                     // 64

    float* out     = (float*)d_out;
    float* sums    = out;                     // [N, D]
    float* last_ts = out + (long long)N * D;  // [N]
    float* counts  = last_ts + N;             // [N]

    const int NB = (N + SCAN_BLK - 1) / SCAN_BLK;

    // 1. zero hist + last_ts
    zero_kernel<<<(N + 255) / 256, 256>>>(last_ts, N);
    // 2. histogram + timestamp max
    hist_kernel<<<(B + 255) / 256, 256>>>(node_ids, timestamps, last_ts, B);
    // 3-5. exclusive scan of histogram -> offsets (+ cursor init)
    scan1_kernel<<<NB, SCAN_BLK>>>(N);
    scan2_kernel<<<1, SCAN_BLK>>>(NB);
    scan3_kernel<<<NB, SCAN_BLK>>>(N);
    // 6. bin event indices per node
    bin_kernel<<<(B + 255) / 256, 256>>>(node_ids, B);
    // 7. gather + mean, one warp per node
    {
        int thr = 256;                        // 8 warps per CTA
        int warps_per_blk = thr / 32;
        int blocks = (N + warps_per_blk - 1) / warps_per_blk;
        sum_kernel<<<blocks, thr>>>((const float4*)messages, (float4*)sums,
                                    counts, N, Dq);
    }
}